// round 12
// baseline (speedup 1.0000x reference)
#include <cuda_runtime.h>
#include <cuda_bf16.h>
#include <math.h>
#include <stdint.h>

#define NN 100000
#define NE 800000
#define H  128
#define NC 64
#define LN_EPS 1e-5f
#define GEMM_BLOCKS 148
#define GEMM_THREADS 512
#define GEMM_WARPS (GEMM_THREADS/32)

#define TILE_M 128
#define NT ((NN + TILE_M - 1)/TILE_M)   // 782

// tcgen05 is an 'a'-feature: only emit it in the sm_103a SASS pass.
#if defined(__CUDA_ARCH__) && !defined(__CUDA_ARCH_FEAT_SM103_ALL) && !defined(__CUDA_ARCH_FEAT_SM100_ALL)
#define USE_TCGEN05 0
#else
#define USE_TCGEN05 1
#endif

// -------- scratch (BSS zero at load; g_deg/g_flag re-zeroed at end of call) --------
__device__ float g_hA[NN*H];
__device__ float g_hB[NN*H];
__device__ float g_agg[NN*H];
__device__ float g_inv[NN];
__device__ int   g_deg[NN];
__device__ int   g_off[NN+1];
__device__ int   g_cur[NN];
__device__ int   g_col[NE];
__device__ int   g_flag;

// ============ generic PTX helpers ============
__device__ __forceinline__ uint32_t smem_u32(const void* p) {
    uint32_t a;
    asm("{ .reg .u64 t; cvta.to.shared.u64 t, %1; cvt.u32.u64 %0, t; }" : "=r"(a) : "l"(p));
    return a;
}
__device__ __forceinline__ uint32_t elect_one() {
    uint32_t p;
    asm volatile("{\n\t.reg .pred p;\n\telect.sync _|p, 0xFFFFFFFF;\n\tselp.b32 %0,1,0,p;\n\t}" : "=r"(p));
    return p;
}
__device__ __forceinline__ void mbar_init(uint32_t mbar, uint32_t cnt) {
    asm volatile("mbarrier.init.shared.b64 [%0], %1;" :: "r"(mbar), "r"(cnt) : "memory");
}
__device__ __forceinline__ void mbar_wait(uint32_t mbar, uint32_t parity) {
    uint32_t done;
    asm volatile("{\n\t.reg .pred p;\n\t"
        "mbarrier.try_wait.parity.acquire.cta.shared::cta.b64 p, [%1], %2;\n\t"
        "selp.b32 %0,1,0,p;\n\t}" : "=r"(done) : "r"(mbar), "r"(parity) : "memory");
    if (!done) {
        asm volatile("{\n\t.reg .pred P1;\n\t"
            "WL_%=:\n\t"
            "mbarrier.try_wait.parity.acquire.cta.shared::cta.b64 P1, [%0], %1, 0x989680;\n\t"
            "@P1 bra.uni WD_%=;\n\t"
            "bra.uni WL_%=;\n\t"
            "WD_%=:\n\t}" :: "r"(mbar), "r"(parity) : "memory");
    }
}
__device__ __forceinline__ void fence_async_smem() {
    asm volatile("fence.proxy.async.shared::cta;" ::: "memory");
}

#if USE_TCGEN05
__device__ __forceinline__ void tmem_alloc(uint32_t smem_dst, uint32_t ncols) {
    asm volatile("tcgen05.alloc.cta_group::1.sync.aligned.shared::cta.b32 [%0], %1;"
                 :: "r"(smem_dst), "r"(ncols) : "memory");
}
__device__ __forceinline__ void tmem_dealloc(uint32_t tmem, uint32_t ncols) {
    asm volatile("tcgen05.relinquish_alloc_permit.cta_group::1.sync.aligned;");
    asm volatile("tcgen05.dealloc.cta_group::1.sync.aligned.b32 %0, %1;" :: "r"(tmem), "r"(ncols));
}
__device__ __forceinline__ void tc_commit(uint32_t mbar) {
    asm volatile("tcgen05.commit.cta_group::1.mbarrier::arrive::one.shared::cluster.b64 [%0];"
                 :: "r"(mbar) : "memory");
}
__device__ __forceinline__ void tc_fence_after() {
    asm volatile("tcgen05.fence::after_thread_sync;" ::: "memory");
}
__device__ __forceinline__ void tc_fence_before() {
    asm volatile("tcgen05.fence::before_thread_sync;" ::: "memory");
}
__device__ __forceinline__ void tc_wait_ld() {
    asm volatile("tcgen05.wait::ld.sync.aligned;" ::: "memory");
}
__device__ __forceinline__ void mma_bf16_ss(uint32_t d, uint64_t ad, uint64_t bd,
                                            uint32_t idesc, uint32_t en) {
    asm volatile("{\n\t.reg .pred p;\n\tsetp.ne.u32 p, %5, 0;\n\t"
        "tcgen05.mma.cta_group::1.kind::f16 [%0], %1, %2, %3, {%4,%4,%4,%4}, p;\n\t}"
        :: "r"(d), "l"(ad), "l"(bd), "r"(idesc), "r"(0u), "r"(en) : "memory");
}
__device__ __forceinline__ void ldtm_x32(uint32_t* r, uint32_t addr) {
    asm volatile("tcgen05.ld.sync.aligned.32x32b.x32.b32 "
        "{%0,%1,%2,%3,%4,%5,%6,%7,%8,%9,%10,%11,%12,%13,%14,%15,"
        "%16,%17,%18,%19,%20,%21,%22,%23,%24,%25,%26,%27,%28,%29,%30,%31}, [%32];"
        : "=r"(r[0]),"=r"(r[1]),"=r"(r[2]),"=r"(r[3]),"=r"(r[4]),"=r"(r[5]),"=r"(r[6]),"=r"(r[7]),
          "=r"(r[8]),"=r"(r[9]),"=r"(r[10]),"=r"(r[11]),"=r"(r[12]),"=r"(r[13]),"=r"(r[14]),"=r"(r[15]),
          "=r"(r[16]),"=r"(r[17]),"=r"(r[18]),"=r"(r[19]),"=r"(r[20]),"=r"(r[21]),"=r"(r[22]),"=r"(r[23]),
          "=r"(r[24]),"=r"(r[25]),"=r"(r[26]),"=r"(r[27]),"=r"(r[28]),"=r"(r[29]),"=r"(r[30]),"=r"(r[31])
        : "r"(addr));
}
#endif

static __device__ __forceinline__ uint64_t make_desc(uint32_t addr) {
    const uint64_t base = (uint64_t(2) << 61) | (uint64_t(1) << 46)
                        | (uint64_t(64) << 32) | (uint64_t(1) << 16);
    return base | ((uint64_t)(addr >> 4) & 0x3FFF);
}

#define MMA_IDESC   0x8200490u   // M=128 N=128 bf16->f32
#define MMA_IDESC64 0x8100490u   // M=128 N=64  bf16->f32

// -------- layer kernel smem layout --------
#define SM_TMEM  0
#define SM_MBAR  8            // two mbarriers: +0, +8
#define SM_BIAS  64
#define SM_GAM   576
#define SM_BET   1088
#define SM_BH    2048                       // B hi: 128 x 256 bf16 (64KB)
#define SM_BL    (SM_BH + 65536)            // B lo (64KB)
#define SM_A     (SM_BL + 65536)            // A: 2 buffers x (hi 16KB + lo 16KB) = 64KB
#define SM_EPI   SM_A                       // epilogue transpose buffer OVERLAPS A
#define EPI_BYTES (128*129*4)               // 66048
#define SM_TOTAL (SM_A + EPI_BYTES)         // 199168 B

// -------- final kernel smem layout --------
#define SMF_TMEM  0
#define SMF_MBAR  8
#define SMF_BF    64
#define SMF_BH    1024                       // Wf hi: 64x128 bf16 (16KB)
#define SMF_BL    (SMF_BH + 16384)
#define SMF_A     (SMF_BL + 16384)           // 2 bufs x (16KB hi + 16KB lo)
#define SMF_TOTAL (SMF_A + 65536)            // 99328

// SW128 offsets
__device__ __forceinline__ uint32_t tile_off(uint32_t r, uint32_t c) {
    uint32_t byte = (((c >> 6) * 16u + (r >> 3)) * 1024u) + (r & 7u) * 128u + (c & 63u) * 2u;
    return byte ^ ((byte >> 3) & 0x70u);
}
__device__ __forceinline__ uint32_t tile_off64(uint32_t r, uint32_t c) {
    uint32_t byte = (r >> 3) * 1024u + (r & 7u) * 128u + c * 2u;
    return byte ^ ((byte >> 3) & 0x70u);
}
__device__ __forceinline__ uint32_t tile_off8(uint32_t r, uint32_t c) {
    uint32_t byte = (((c >> 6) * 8u + (r >> 3)) * 1024u) + (r & 7u) * 128u + (c & 63u) * 2u;
    return byte ^ ((byte >> 3) & 0x70u);
}

__device__ __forceinline__ void cvt_split(float4 v, uint2& uh, uint2& ul) {
    __nv_bfloat162 h01, h23, l01, l23;
    h01.x = __float2bfloat16(v.x); h01.y = __float2bfloat16(v.y);
    h23.x = __float2bfloat16(v.z); h23.y = __float2bfloat16(v.w);
    l01.x = __float2bfloat16(v.x - __bfloat162float(h01.x));
    l01.y = __float2bfloat16(v.y - __bfloat162float(h01.y));
    l23.x = __float2bfloat16(v.z - __bfloat162float(h23.x));
    l23.y = __float2bfloat16(v.w - __bfloat162float(h23.y));
    uh.x = *(uint32_t*)&h01; uh.y = *(uint32_t*)&h23;
    ul.x = *(uint32_t*)&l01; ul.y = *(uint32_t*)&l23;
}

// ============ CSR: count, then merged scan+scatter ============
__global__ void k_count(const int* __restrict__ ei) {
    int e = blockIdx.x*blockDim.x + threadIdx.x;
    if (e < NE) atomicAdd(&g_deg[ei[e]], 1);
}
// block 0 (1024 threads) scans, publishes g_flag; all blocks then scatter.
// Block 0 is wave-1 resident -> no deadlock. (Pattern proven to run in R8.)
__global__ void k_scan_scatter(const int* __restrict__ ei) {
    int t = threadIdx.x;
    if (blockIdx.x == 0) {
        __shared__ int ps[1024];
        const int chunk = (NN + 1023)/1024;
        int b = t*chunk;
        int e = min(b + chunk, NN);
        int s = 0;
#pragma unroll 4
        for (int i=b;i<e;i++) s += g_deg[i];
        ps[t] = s; __syncthreads();
        for (int o=1;o<1024;o<<=1) {
            int v = (t>=o) ? ps[t-o] : 0;
            __syncthreads();
            ps[t] += v;
            __syncthreads();
        }
        int run = (t==0) ? 0 : ps[t-1];
#pragma unroll 4
        for (int i=b;i<e;i++) {
            int d = g_deg[i];
            g_off[i] = run; g_cur[i] = run;
            g_inv[i] = 1.0f / (float)max(d, 1);
            run += d;
        }
        if (t==1023) g_off[NN] = ps[1023];
        __threadfence();
        __syncthreads();
        if (t==0) atomicExch(&g_flag, 1);
    } else {
        if (t==0) {
            while (atomicAdd(&g_flag, 0) == 0) { __nanosleep(256); }
        }
        __syncthreads();
        __threadfence();
    }
    int e = blockIdx.x*blockDim.x + t;
    if (e < NE) {
        int d = ei[e], s = ei[NE + e];
        int p = atomicAdd(&g_cur[d], 1);
        g_col[p] = s;
    }
}
__global__ void k_cleanup() {
    int i = blockIdx.x*blockDim.x + threadIdx.x;
    if (i < NN) g_deg[i] = 0;
    if (i == 0) g_flag = 0;
}

// ============ mean aggregation ============
__global__ void k_agg(const float* __restrict__ hin) {
    int w    = (blockIdx.x*blockDim.x + threadIdx.x) >> 5;
    int lane = threadIdx.x & 31;
    if (w >= NN) return;
    int b0 = g_off[w], b1 = g_off[w+1];
    const float4* h4 = (const float4*)hin;
    float4 acc = {0.f,0.f,0.f,0.f};
    for (int j0 = b0; j0 < b1; j0 += 32) {
        int jj = j0 + lane;
        int myc = (jj < b1) ? g_col[jj] : 0;
        int cnt = min(32, b1 - j0);
#pragma unroll 8
        for (int k = 0; k < cnt; k++) {
            int s = __shfl_sync(0xffffffffu, myc, k);
            float4 v = h4[s*32 + lane];
            acc.x += v.x; acc.y += v.y; acc.z += v.z; acc.w += v.w;
        }
    }
    float iv = g_inv[w];
    float4 o = {acc.x*iv, acc.y*iv, acc.z*iv, acc.w*iv};
    ((float4*)g_agg)[w*32 + lane] = o;
}

// ============ layer: tcgen05 dual-GEMM + bias + LN + ReLU (prefetch-pipelined) ============
__global__ void __launch_bounds__(GEMM_THREADS, 1)
k_layer_mma(const float* __restrict__ hin, float* __restrict__ hout,
            const float* __restrict__ Wl, const float* __restrict__ bl,
            const float* __restrict__ Wr, const float* __restrict__ gamma,
            const float* __restrict__ beta) {
    extern __shared__ char smem[];
    uint32_t sb = smem_u32(smem);
    int tid = threadIdx.x, wid = tid >> 5, lane = tid & 31;

#if USE_TCGEN05
    if (wid == 0) tmem_alloc(sb + SM_TMEM, 128);
    if (tid == 0) { mbar_init(sb + SM_MBAR, 1); mbar_init(sb + SM_MBAR + 8, 1); }
    __syncthreads();
    uint32_t tmem;
    asm volatile("ld.shared.b32 %0, [%1];" : "=r"(tmem) : "r"(sb + SM_TMEM));

    if (tid < H) {
        ((float*)(smem + SM_BIAS))[tid] = bl[tid];
        ((float*)(smem + SM_GAM ))[tid] = gamma[tid];
        ((float*)(smem + SM_BET ))[tid] = beta[tid];
    }
    for (int idx = tid; idx < 8192; idx += GEMM_THREADS) {
        int m   = idx >> 12;
        int rem = idx & 4095;
        int c   = rem >> 5;
        int f   = rem & 31;
        float4 v = ((const float4*)(m ? Wr : Wl))[c*32 + f];
        uint32_t kcol = (uint32_t)(m*128 + f*4);
        uint2 uh, ul; cvt_split(v, uh, ul);
        uint32_t off = tile_off((uint32_t)c, kcol);
        *(uint2*)(smem + SM_BH + off) = uh;
        *(uint2*)(smem + SM_BL + off) = ul;
    }

    uint64_t dBh = make_desc(sb + SM_BH), dBl = make_desc(sb + SM_BL);
    const float* bls = (const float*)(smem + SM_BIAS);
    const float* gms = (const float*)(smem + SM_GAM);
    const float* bts = (const float*)(smem + SM_BET);
    float* eps = (float*)(smem + SM_EPI);

    int cnt[2] = {0,0}, ws[2] = {0,0};
    int r_row = tid >> 2, q = tid & 3;
    const float4 zf4 = make_float4(0.f,0.f,0.f,0.f);
    float4 v0, v1, v2, v3;

#define LD_CHUNK(TB, C) do {                                            \
        const float4* _s4 = (const float4*)(((C) < 2) ? g_agg : hin);   \
        int _nd = (TB) + r_row;                                         \
        bool _val = _nd < NN;                                           \
        int _fb = ((C) & 1) * 16 + q * 4;                               \
        v0 = _val ? _s4[_nd*32 + _fb + 0] : zf4;                        \
        v1 = _val ? _s4[_nd*32 + _fb + 1] : zf4;                        \
        v2 = _val ? _s4[_nd*32 + _fb + 2] : zf4;                        \
        v3 = _val ? _s4[_nd*32 + _fb + 3] : zf4;                        \
    } while (0)

    int tile0 = blockIdx.x;
    if (tile0 < NT) LD_CHUNK(tile0 * TILE_M, 0);

    for (int tile = tile0; tile < NT; tile += gridDim.x) {
        int tb = tile * TILE_M;

#pragma unroll
        for (int c = 0; c < 4; c++) {
            int p = c & 1;
            uint32_t mb = sb + SM_MBAR + p*8;
            if (ws[p] < cnt[p]) { mbar_wait(mb, (cnt[p]-1) & 1); ws[p] = cnt[p]; }
            {
                char* aH = smem + SM_A + p*32768;
                char* aL = aH + 16384;
                uint2 uh, ul; uint32_t off;
                off = tile_off64((uint32_t)r_row, (uint32_t)(q*16 + 0));
                cvt_split(v0, uh, ul); *(uint2*)(aH+off)=uh; *(uint2*)(aL+off)=ul;
                off = tile_off64((uint32_t)r_row, (uint32_t)(q*16 + 4));
                cvt_split(v1, uh, ul); *(uint2*)(aH+off)=uh; *(uint2*)(aL+off)=ul;
                off = tile_off64((uint32_t)r_row, (uint32_t)(q*16 + 8));
                cvt_split(v2, uh, ul); *(uint2*)(aH+off)=uh; *(uint2*)(aL+off)=ul;
                off = tile_off64((uint32_t)r_row, (uint32_t)(q*16 + 12));
                cvt_split(v3, uh, ul); *(uint2*)(aH+off)=uh; *(uint2*)(aL+off)=ul;
            }
            if (c < 3) {
                LD_CHUNK(tb, c + 1);
            } else {
                int nt2 = tile + gridDim.x;
                if (nt2 < NT) LD_CHUNK(nt2 * TILE_M, 0);
            }
            fence_async_smem();
            __syncthreads();
            if (wid == 0 && elect_one()) {
                uint64_t dAh = make_desc(sb + SM_A + p*32768);
                uint64_t dAl = make_desc(sb + SM_A + p*32768 + 16384);
#pragma unroll
                for (int k = 0; k < 4; k++) {
                    uint64_t ao = (uint64_t)(k*2);
                    int ks = c*4 + k;
                    uint64_t bo = (uint64_t)((ks >> 2)*1024 + (ks & 3)*2);
                    mma_bf16_ss(tmem, dAh + ao, dBh + bo, MMA_IDESC, (c==0 && k==0) ? 0u : 1u);
                    mma_bf16_ss(tmem, dAh + ao, dBl + bo, MMA_IDESC, 1u);
                    mma_bf16_ss(tmem, dAl + ao, dBh + bo, MMA_IDESC, 1u);
                }
                tc_commit(mb);
            }
            cnt[p]++;
        }

        if (ws[1] < cnt[1]) { mbar_wait(sb + SM_MBAR + 8, (cnt[1]-1) & 1); ws[1] = cnt[1]; }
        tc_fence_after();

        if (wid < 4) {
            int row = wid * 32 + lane;
            float s1 = 0.f, s2 = 0.f;
            uint32_t d[32];
#pragma unroll
            for (int g = 0; g < 4; g++) {
                ldtm_x32(d, tmem + g * 32);
                tc_wait_ld();
#pragma unroll
                for (int c = 0; c < 32; c++) {
                    float v = __uint_as_float(d[c]) + bls[g*32 + c];
                    s1 += v; s2 += v * v;
                }
            }
            float mu  = s1 * (1.0f / H);
            float var = s2 * (1.0f / H) - mu * mu;
            float rs  = rsqrtf(var + LN_EPS);
#pragma unroll
            for (int g = 0; g < 4; g++) {
                ldtm_x32(d, tmem + g * 32);
                tc_wait_ld();
#pragma unroll
                for (int c = 0; c < 32; c++) {
                    float v = __uint_as_float(d[c]) + bls[g*32 + c];
                    eps[row*129 + g*32 + c] =
                        fmaxf((v - mu) * rs * gms[g*32 + c] + bts[g*32 + c], 0.f);
                }
            }
            tc_fence_before();
        }
        __syncthreads();
        {
            int r0 = wid * 8;
#pragma unroll
            for (int rr = 0; rr < 8; rr++) {
                int r = r0 + rr;
                int node = tb + r;
                if (node < NN) {
#pragma unroll
                    for (int u = 0; u < 4; u++)
                        hout[(size_t)node*H + u*32 + lane] = eps[r*129 + u*32 + lane];
                }
            }
        }
        __syncthreads();
    }
#undef LD_CHUNK
    if (ws[0] < cnt[0]) { mbar_wait(sb + SM_MBAR,     (cnt[0]-1) & 1); ws[0] = cnt[0]; }
    if (ws[1] < cnt[1]) { mbar_wait(sb + SM_MBAR + 8, (cnt[1]-1) & 1); ws[1] = cnt[1]; }
    __syncthreads();
    if (wid == 0) tmem_dealloc(tmem, 128);

#else  // ===== FFMA fallback (compute_103 PTX pass; never selected on GB300) =====
    float* sW = (float*)(smem + 2048);
    float* sA = sW + 256*H;
    for (int idx = tid; idx < H*H; idx += GEMM_THREADS) {
        int c = idx >> 7, k = idx & 127;
        sW[k*H + c]     = Wl[idx];
        sW[(k+H)*H + c] = Wr[idx];
    }
    __syncthreads();
    float4 blv = ((const float4*)bl)[lane];
    float4 gv  = ((const float4*)gamma)[lane];
    float4 bv  = ((const float4*)beta)[lane];
    const float4* h4 = (const float4*)hin;
    const float4* a4 = (const float4*)g_agg;
    float* sAw = sA + wid*256;
    for (int node = blockIdx.x*GEMM_WARPS + wid; node < NN; node += GEMM_BLOCKS*GEMM_WARPS) {
        *(float4*)(sAw + lane*4)       = a4[node*32 + lane];
        *(float4*)(sAw + 128 + lane*4) = h4[node*32 + lane];
        __syncwarp();
        float4 acc = make_float4(0.f,0.f,0.f,0.f);
        for (int k = 0; k < 256; k++) {
            float aa = sAw[k];
            float4 wv = *(const float4*)(sW + k*H + lane*4);
            acc.x += aa*wv.x; acc.y += aa*wv.y; acc.z += aa*wv.z; acc.w += aa*wv.w;
        }
        acc.x += blv.x; acc.y += blv.y; acc.z += blv.z; acc.w += blv.w;
        float s1 = acc.x + acc.y + acc.z + acc.w;
        float s2 = acc.x*acc.x + acc.y*acc.y + acc.z*acc.z + acc.w*acc.w;
        for (int o = 16; o > 0; o >>= 1) {
            s1 += __shfl_xor_sync(0xffffffffu, s1, o);
            s2 += __shfl_xor_sync(0xffffffffu, s2, o);
        }
        float mu  = s1 * (1.0f/H);
        float var = s2 * (1.0f/H) - mu*mu;
        float r   = rsqrtf(var + LN_EPS);
        float4 o4;
        o4.x = fmaxf((acc.x - mu)*r*gv.x + bv.x, 0.0f);
        o4.y = fmaxf((acc.y - mu)*r*gv.y + bv.y, 0.0f);
        o4.z = fmaxf((acc.z - mu)*r*gv.z + bv.z, 0.0f);
        o4.w = fmaxf((acc.w - mu)*r*gv.w + bv.w, 0.0f);
        ((float4*)hout)[(size_t)node*32 + lane] = o4;
        __syncwarp();
    }
#endif
}

// ============ final: tcgen05 projection (N=64) + log_softmax (prefetch-pipelined) ============
__global__ void __launch_bounds__(GEMM_THREADS, 1)
k_final_mma(const float* __restrict__ hin, const float* __restrict__ Wf,
            const float* __restrict__ bf, float* __restrict__ out) {
    extern __shared__ char smem[];
    uint32_t sb = smem_u32(smem);
    int tid = threadIdx.x, wid = tid >> 5, lane = tid & 31;

#if USE_TCGEN05
    if (wid == 0) tmem_alloc(sb + SMF_TMEM, 128);
    if (tid == 0) { mbar_init(sb + SMF_MBAR, 1); mbar_init(sb + SMF_MBAR + 8, 1); }
    __syncthreads();
    uint32_t tmem;
    asm volatile("ld.shared.b32 %0, [%1];" : "=r"(tmem) : "r"(sb + SMF_TMEM));

    if (tid < NC) ((float*)(smem + SMF_BF))[tid] = bf[tid];
    for (int idx = tid; idx < 2048; idx += GEMM_THREADS) {
        int c = idx >> 5, f = idx & 31;
        float4 v = ((const float4*)Wf)[c*32 + f];
        uint2 uh, ul; cvt_split(v, uh, ul);
        uint32_t off = tile_off8((uint32_t)c, (uint32_t)(f*4));
        *(uint2*)(smem + SMF_BH + off) = uh;
        *(uint2*)(smem + SMF_BL + off) = ul;
    }

    uint64_t dBh = make_desc(sb + SMF_BH), dBl = make_desc(sb + SMF_BL);
    const float* bfs = (const float*)(smem + SMF_BF);

    int cnt[2] = {0,0}, ws[2] = {0,0};
    int r_row = tid >> 2, q = tid & 3;
    const float4 zf4 = make_float4(0.f,0.f,0.f,0.f);
    float4 v0, v1, v2, v3;

#define LD_CHUNKF(TB, C) do {                                           \
        const float4* _s4 = (const float4*)hin;                         \
        int _nd = (TB) + r_row;                                         \
        bool _val = _nd < NN;                                           \
        int _fb = (C) * 16 + q * 4;                                     \
        v0 = _val ? _s4[_nd*32 + _fb + 0] : zf4;                        \
        v1 = _val ? _s4[_nd*32 + _fb + 1] : zf4;                        \
        v2 = _val ? _s4[_nd*32 + _fb + 2] : zf4;                        \
        v3 = _val ? _s4[_nd*32 + _fb + 3] : zf4;                        \
    } while (0)

    int tile0 = blockIdx.x;
    if (tile0 < NT) LD_CHUNKF(tile0 * TILE_M, 0);

    for (int tile = tile0; tile < NT; tile += gridDim.x) {
        int tb = tile * TILE_M;
#pragma unroll
        for (int c = 0; c < 2; c++) {
            int p = c;
            uint32_t mb = sb + SMF_MBAR + p*8;
            if (ws[p] < cnt[p]) { mbar_wait(mb, (cnt[p]-1) & 1); ws[p] = cnt[p]; }
            {
                char* aH = smem + SMF_A + p*32768;
                char* aL = aH + 16384;
                uint2 uh, ul; uint32_t off;
                off = tile_off64((uint32_t)r_row, (uint32_t)(q*16 + 0));
                cvt_split(v0, uh, ul); *(uint2*)(aH+off)=uh; *(uint2*)(aL+off)=ul;
                off = tile_off64((uint32_t)r_row, (uint32_t)(q*16 + 4));
                cvt_split(v1, uh, ul); *(uint2*)(aH+off)=uh; *(uint2*)(aL+off)=ul;
                off = tile_off64((uint32_t)r_row, (uint32_t)(q*16 + 8));
                cvt_split(v2, uh, ul); *(uint2*)(aH+off)=uh; *(uint2*)(aL+off)=ul;
                off = tile_off64((uint32_t)r_row, (uint32_t)(q*16 + 12));
                cvt_split(v3, uh, ul); *(uint2*)(aH+off)=uh; *(uint2*)(aL+off)=ul;
            }
            if (c == 0) {
                LD_CHUNKF(tb, 1);
            } else {
                int nt2 = tile + gridDim.x;
                if (nt2 < NT) LD_CHUNKF(nt2 * TILE_M, 0);
            }
            fence_async_smem();
            __syncthreads();
            if (wid == 0 && elect_one()) {
                uint64_t dAh = make_desc(sb + SMF_A + p*32768);
                uint64_t dAl = make_desc(sb + SMF_A + p*32768 + 16384);
#pragma unroll
                for (int k = 0; k < 4; k++) {
                    uint64_t ao = (uint64_t)(k*2);
                    int ks = c*4 + k;
                    uint64_t bo = (uint64_t)((ks >> 2)*512 + (ks & 3)*2);
                    mma_bf16_ss(tmem, dAh + ao, dBh + bo, MMA_IDESC64, (c==0 && k==0) ? 0u : 1u);
                    mma_bf16_ss(tmem, dAh + ao, dBl + bo, MMA_IDESC64, 1u);
                    mma_bf16_ss(tmem, dAl + ao, dBh + bo, MMA_IDESC64, 1u);
                }
                tc_commit(mb);
            }
            cnt[p]++;
        }

        if (ws[1] < cnt[1]) { mbar_wait(sb + SMF_MBAR + 8, (cnt[1]-1) & 1); ws[1] = cnt[1]; }
        tc_fence_after();

        if (wid < 4) {
            int row = wid * 32 + lane;
            int node = tb + row;
            uint32_t d0[32], d1[32];
            ldtm_x32(d0, tmem);
            ldtm_x32(d1, tmem + 32);
            tc_wait_ld();
            float l0[32], l1[32];
            float m = -1e30f;
#pragma unroll
            for (int j = 0; j < 32; j++) {
                l0[j] = __uint_as_float(d0[j]) + bfs[j];
                l1[j] = __uint_as_float(d1[j]) + bfs[32 + j];
                m = fmaxf(m, fmaxf(l0[j], l1[j]));
            }
            float se = 0.f;
#pragma unroll
            for (int j = 0; j < 32; j++) se += expf(l0[j] - m) + expf(l1[j] - m);
            float lse = logf(se) + m;
            if (node < NN) {
#pragma unroll
                for (int j = 0; j < 32; j++) {
                    out[(size_t)node*NC + j]      = l0[j] - lse;
                    out[(size_t)node*NC + 32 + j] = l1[j] - lse;
                }
            }
            tc_fence_before();
        }
        __syncthreads();
    }
#undef LD_CHUNKF
    if (ws[0] < cnt[0]) { mbar_wait(sb + SMF_MBAR,     (cnt[0]-1) & 1); ws[0] = cnt[0]; }
    if (ws[1] < cnt[1]) { mbar_wait(sb + SMF_MBAR + 8, (cnt[1]-1) & 1); ws[1] = cnt[1]; }
    __syncthreads();
    if (wid == 0) tmem_dealloc(tmem, 128);

#else  // ===== FFMA fallback =====
    __shared__ float sW[H*NC];
    for (int idx = tid; idx < NC*H; idx += GEMM_THREADS) {
        int c = idx >> 7, k = idx & 127;
        sW[k*NC + c] = Wf[idx];
    }
    __syncthreads();
    float bf0 = bf[lane], bf1 = bf[32 + lane];
    for (int node = blockIdx.x*GEMM_WARPS + wid; node < NN; node += GEMM_BLOCKS*GEMM_WARPS) {
        float al[4];
#pragma unroll
        for (int q2=0;q2<4;q2++) al[q2] = hin[(size_t)node*H + q2*32 + lane];
        float acc0 = 0.f, acc1 = 0.f;
#pragma unroll
        for (int q2=0;q2<4;q2++) {
            float aq = al[q2];
#pragma unroll
            for (int kk=0;kk<32;kk++) {
                float a = __shfl_sync(0xffffffffu, aq, kk);
                acc0 += a * sW[(q2*32+kk)*NC + lane];
                acc1 += a * sW[(q2*32+kk)*NC + 32 + lane];
            }
        }
        acc0 += bf0; acc1 += bf1;
        float m = fmaxf(acc0, acc1);
#pragma unroll
        for (int o=16;o>0;o>>=1) m = fmaxf(m, __shfl_xor_sync(0xffffffffu, m, o));
        float se = expf(acc0 - m) + expf(acc1 - m);
#pragma unroll
        for (int o=16;o>0;o>>=1) se += __shfl_xor_sync(0xffffffffu, se, o);
        float lse = logf(se);
        out[(size_t)node*NC + lane]      = acc0 - m - lse;
        out[(size_t)node*NC + 32 + lane] = acc1 - m - lse;
    }
#endif
}

extern "C" void kernel_launch(void* const* d_in, const int* in_sizes, int n_in,
                              void* d_out, int out_size) {
    const float* x     = (const float*)d_in[0];
    const int*   ei    = (const int*)  d_in[1];
    const float* Wl    = (const float*)d_in[2];
    const float* bl    = (const float*)d_in[3];
    const float* Wr    = (const float*)d_in[4];
    const float* gamma = (const float*)d_in[5];
    const float* beta  = (const float*)d_in[6];
    const float* Wf    = (const float*)d_in[7];
    const float* bf    = (const float*)d_in[8];
    float* out = (float*)d_out;

    cudaFuncSetAttribute(k_layer_mma, cudaFuncAttributeMaxDynamicSharedMemorySize, SM_TOTAL);
    cudaFuncSetAttribute(k_final_mma, cudaFuncAttributeMaxDynamicSharedMemorySize, SMF_TOTAL);

    float *hA, *hB;
    cudaGetSymbolAddress((void**)&hA, g_hA);
    cudaGetSymbolAddress((void**)&hB, g_hB);

    // g_deg/g_flag are zero here (BSS init on first call; k_cleanup at end of every call)
    k_count       <<<(NE+255)/256, 256>>>(ei);      // launch 0
    k_scan_scatter<<<(NE+1023)/1024, 1024>>>(ei);   // launch 1

    const float* hin = x;
    float* houts[3] = {hA, hB, hA};
    for (int i=0;i<3;i++) {
        k_agg<<<(NN+7)/8, 256>>>(hin);              // launch 2 (i=0)
        k_layer_mma<<<GEMM_BLOCKS, GEMM_THREADS, SM_TOTAL>>>(hin, houts[i],  // launch 3 (i=0) -> ncu
            Wl + i*H*H, bl + i*H, Wr + i*H*H, gamma + i*H, beta + i*H);
        hin = houts[i];
    }
    k_final_mma<<<GEMM_BLOCKS, GEMM_THREADS, SMF_TOTAL>>>(hin, Wf, bf, out);
    k_cleanup<<<(NN+255)/256, 256>>>();
}

// round 13
// speedup vs baseline: 1.0216x; 1.0216x over previous
#include <cuda_runtime.h>
#include <cuda_bf16.h>
#include <math.h>
#include <stdint.h>

#define NN 100000
#define NE 800000
#define H  128
#define NC 64
#define LN_EPS 1e-5f
#define GEMM_BLOCKS 148
#define GEMM_THREADS 512
#define GEMM_WARPS (GEMM_THREADS/32)

#define TILE_M 128
#define NT ((NN + TILE_M - 1)/TILE_M)   // 782

// tcgen05 is an 'a'-feature: only emit it in the sm_103a SASS pass.
#if defined(__CUDA_ARCH__) && !defined(__CUDA_ARCH_FEAT_SM103_ALL) && !defined(__CUDA_ARCH_FEAT_SM100_ALL)
#define USE_TCGEN05 0
#else
#define USE_TCGEN05 1
#endif

// -------- scratch (BSS zero at load; g_deg re-zeroed at end of call) --------
__device__ float g_hA[NN*H];
__device__ float g_hB[NN*H];
// agg result, pre-converted to bf16 hi/lo and pre-swizzled per (tile, chunk):
// region (t, c) = 16KB holding rows 0..127 x 64 bf16 cols at tile_off64 offsets.
// rows for nodes >= NN are never written -> stay BSS-zero (correct padding).
__device__ uint8_t g_aggH[(size_t)NT * 2 * 16384];
__device__ uint8_t g_aggL[(size_t)NT * 2 * 16384];
__device__ float g_inv[NN];
__device__ int   g_deg[NN];
__device__ int   g_off[NN+1];
__device__ int   g_cur[NN];
__device__ int   g_col[NE];

// ============ generic PTX helpers ============
__device__ __forceinline__ uint32_t smem_u32(const void* p) {
    uint32_t a;
    asm("{ .reg .u64 t; cvta.to.shared.u64 t, %1; cvt.u32.u64 %0, t; }" : "=r"(a) : "l"(p));
    return a;
}
__device__ __forceinline__ uint32_t elect_one() {
    uint32_t p;
    asm volatile("{\n\t.reg .pred p;\n\telect.sync _|p, 0xFFFFFFFF;\n\tselp.b32 %0,1,0,p;\n\t}" : "=r"(p));
    return p;
}
__device__ __forceinline__ void mbar_init(uint32_t mbar, uint32_t cnt) {
    asm volatile("mbarrier.init.shared.b64 [%0], %1;" :: "r"(mbar), "r"(cnt) : "memory");
}
__device__ __forceinline__ void mbar_wait(uint32_t mbar, uint32_t parity) {
    uint32_t done;
    asm volatile("{\n\t.reg .pred p;\n\t"
        "mbarrier.try_wait.parity.acquire.cta.shared::cta.b64 p, [%1], %2;\n\t"
        "selp.b32 %0,1,0,p;\n\t}" : "=r"(done) : "r"(mbar), "r"(parity) : "memory");
    if (!done) {
        asm volatile("{\n\t.reg .pred P1;\n\t"
            "WL_%=:\n\t"
            "mbarrier.try_wait.parity.acquire.cta.shared::cta.b64 P1, [%0], %1, 0x989680;\n\t"
            "@P1 bra.uni WD_%=;\n\t"
            "bra.uni WL_%=;\n\t"
            "WD_%=:\n\t}" :: "r"(mbar), "r"(parity) : "memory");
    }
}
__device__ __forceinline__ void fence_async_smem() {
    asm volatile("fence.proxy.async.shared::cta;" ::: "memory");
}

#if USE_TCGEN05
__device__ __forceinline__ void tmem_alloc(uint32_t smem_dst, uint32_t ncols) {
    asm volatile("tcgen05.alloc.cta_group::1.sync.aligned.shared::cta.b32 [%0], %1;"
                 :: "r"(smem_dst), "r"(ncols) : "memory");
}
__device__ __forceinline__ void tmem_dealloc(uint32_t tmem, uint32_t ncols) {
    asm volatile("tcgen05.relinquish_alloc_permit.cta_group::1.sync.aligned;");
    asm volatile("tcgen05.dealloc.cta_group::1.sync.aligned.b32 %0, %1;" :: "r"(tmem), "r"(ncols));
}
__device__ __forceinline__ void tc_commit(uint32_t mbar) {
    asm volatile("tcgen05.commit.cta_group::1.mbarrier::arrive::one.shared::cluster.b64 [%0];"
                 :: "r"(mbar) : "memory");
}
__device__ __forceinline__ void tc_fence_after() {
    asm volatile("tcgen05.fence::after_thread_sync;" ::: "memory");
}
__device__ __forceinline__ void tc_fence_before() {
    asm volatile("tcgen05.fence::before_thread_sync;" ::: "memory");
}
__device__ __forceinline__ void tc_wait_ld() {
    asm volatile("tcgen05.wait::ld.sync.aligned;" ::: "memory");
}
__device__ __forceinline__ void mma_bf16_ss(uint32_t d, uint64_t ad, uint64_t bd,
                                            uint32_t idesc, uint32_t en) {
    asm volatile("{\n\t.reg .pred p;\n\tsetp.ne.u32 p, %5, 0;\n\t"
        "tcgen05.mma.cta_group::1.kind::f16 [%0], %1, %2, %3, {%4,%4,%4,%4}, p;\n\t}"
        :: "r"(d), "l"(ad), "l"(bd), "r"(idesc), "r"(0u), "r"(en) : "memory");
}
__device__ __forceinline__ void ldtm_x32(uint32_t* r, uint32_t addr) {
    asm volatile("tcgen05.ld.sync.aligned.32x32b.x32.b32 "
        "{%0,%1,%2,%3,%4,%5,%6,%7,%8,%9,%10,%11,%12,%13,%14,%15,"
        "%16,%17,%18,%19,%20,%21,%22,%23,%24,%25,%26,%27,%28,%29,%30,%31}, [%32];"
        : "=r"(r[0]),"=r"(r[1]),"=r"(r[2]),"=r"(r[3]),"=r"(r[4]),"=r"(r[5]),"=r"(r[6]),"=r"(r[7]),
          "=r"(r[8]),"=r"(r[9]),"=r"(r[10]),"=r"(r[11]),"=r"(r[12]),"=r"(r[13]),"=r"(r[14]),"=r"(r[15]),
          "=r"(r[16]),"=r"(r[17]),"=r"(r[18]),"=r"(r[19]),"=r"(r[20]),"=r"(r[21]),"=r"(r[22]),"=r"(r[23]),
          "=r"(r[24]),"=r"(r[25]),"=r"(r[26]),"=r"(r[27]),"=r"(r[28]),"=r"(r[29]),"=r"(r[30]),"=r"(r[31])
        : "r"(addr));
}
#endif

static __device__ __forceinline__ uint64_t make_desc(uint32_t addr) {
    const uint64_t base = (uint64_t(2) << 61) | (uint64_t(1) << 46)
                        | (uint64_t(64) << 32) | (uint64_t(1) << 16);
    return base | ((uint64_t)(addr >> 4) & 0x3FFF);
}

#define MMA_IDESC   0x8200490u   // M=128 N=128 bf16->f32
#define MMA_IDESC64 0x8100490u   // M=128 N=64  bf16->f32

// -------- layer kernel smem layout --------
#define SM_TMEM  0
#define SM_MBAR  8            // two mbarriers: +0, +8
#define SM_BIAS  64
#define SM_GAM   576
#define SM_BET   1088
#define SM_BH    2048                       // B hi: 128 x 256 bf16 (64KB)
#define SM_BL    (SM_BH + 65536)            // B lo (64KB)
#define SM_A     (SM_BL + 65536)            // A: 2 buffers x (hi 16KB + lo 16KB) = 64KB
#define SM_EPI   SM_A                       // epilogue transpose buffer OVERLAPS A
#define EPI_BYTES (128*129*4)               // 66048
#define SM_TOTAL (SM_A + EPI_BYTES)         // 199168 B

// -------- final kernel smem layout --------
#define SMF_TMEM  0
#define SMF_MBAR  8
#define SMF_BF    64
#define SMF_BH    1024                       // Wf hi: 64x128 bf16 (16KB)
#define SMF_BL    (SMF_BH + 16384)
#define SMF_A     (SMF_BL + 16384)           // 2 bufs x (16KB hi + 16KB lo)
#define SMF_TOTAL (SMF_A + 65536)            // 99328

// SW128 offsets
__device__ __forceinline__ uint32_t tile_off(uint32_t r, uint32_t c) {
    uint32_t byte = (((c >> 6) * 16u + (r >> 3)) * 1024u) + (r & 7u) * 128u + (c & 63u) * 2u;
    return byte ^ ((byte >> 3) & 0x70u);
}
__device__ __forceinline__ uint32_t tile_off64(uint32_t r, uint32_t c) {
    uint32_t byte = (r >> 3) * 1024u + (r & 7u) * 128u + c * 2u;
    return byte ^ ((byte >> 3) & 0x70u);
}
__device__ __forceinline__ uint32_t tile_off8(uint32_t r, uint32_t c) {
    uint32_t byte = (((c >> 6) * 8u + (r >> 3)) * 1024u) + (r & 7u) * 128u + (c & 63u) * 2u;
    return byte ^ ((byte >> 3) & 0x70u);
}

__device__ __forceinline__ void cvt_split(float4 v, uint2& uh, uint2& ul) {
    __nv_bfloat162 h01, h23, l01, l23;
    h01.x = __float2bfloat16(v.x); h01.y = __float2bfloat16(v.y);
    h23.x = __float2bfloat16(v.z); h23.y = __float2bfloat16(v.w);
    l01.x = __float2bfloat16(v.x - __bfloat162float(h01.x));
    l01.y = __float2bfloat16(v.y - __bfloat162float(h01.y));
    l23.x = __float2bfloat16(v.z - __bfloat162float(h23.x));
    l23.y = __float2bfloat16(v.w - __bfloat162float(h23.y));
    uh.x = *(uint32_t*)&h01; uh.y = *(uint32_t*)&h23;
    ul.x = *(uint32_t*)&l01; ul.y = *(uint32_t*)&l23;
}

// ============ CSR build ============
__global__ void k_count(const int* __restrict__ ei) {
    int e = blockIdx.x*blockDim.x + threadIdx.x;
    if (e < NE) atomicAdd(&g_deg[ei[e]], 1);
}
__global__ void k_scan() {
    __shared__ int ps[1024];
    int t = threadIdx.x;
    const int chunk = (NN + 1023)/1024;
    int b = t*chunk;
    int e = min(b + chunk, NN);
    int s = 0;
#pragma unroll 4
    for (int i=b;i<e;i++) s += g_deg[i];
    ps[t] = s; __syncthreads();
    for (int o=1;o<1024;o<<=1) {
        int v = (t>=o) ? ps[t-o] : 0;
        __syncthreads();
        ps[t] += v;
        __syncthreads();
    }
    int run = (t==0) ? 0 : ps[t-1];
#pragma unroll 4
    for (int i=b;i<e;i++) {
        int d = g_deg[i];
        g_off[i] = run; g_cur[i] = run;
        g_inv[i] = 1.0f / (float)max(d, 1);
        run += d;
    }
    if (t==1023) g_off[NN] = ps[1023];
}
__global__ void k_scatter(const int* __restrict__ ei) {
    int e = blockIdx.x*blockDim.x + threadIdx.x;
    if (e < NE) {
        int d = ei[e], s = ei[NE + e];
        int p = atomicAdd(&g_cur[d], 1);
        g_col[p] = s;
    }
}
__global__ void k_zero_deg() {
    int i = blockIdx.x*blockDim.x + threadIdx.x;
    if (i < NN) g_deg[i] = 0;
}

// ============ mean aggregation -> pre-swizzled bf16 hi/lo ============
__global__ void k_agg(const float* __restrict__ hin) {
    int w    = (blockIdx.x*blockDim.x + threadIdx.x) >> 5;
    int lane = threadIdx.x & 31;
    if (w >= NN) return;
    int b0 = g_off[w], b1 = g_off[w+1];
    const float4* h4 = (const float4*)hin;
    float4 acc = {0.f,0.f,0.f,0.f};
    for (int j0 = b0; j0 < b1; j0 += 32) {
        int jj = j0 + lane;
        int myc = (jj < b1) ? g_col[jj] : 0;
        int cnt = min(32, b1 - j0);
#pragma unroll 8
        for (int k = 0; k < cnt; k++) {
            int s = __shfl_sync(0xffffffffu, myc, k);
            float4 v = h4[s*32 + lane];
            acc.x += v.x; acc.y += v.y; acc.z += v.z; acc.w += v.w;
        }
    }
    float iv = g_inv[w];
    acc.x *= iv; acc.y *= iv; acc.z *= iv; acc.w *= iv;
    // write bf16 hi/lo at the swizzled position k_layer's A-chunk expects
    uint2 uh, ul; cvt_split(acc, uh, ul);
    int tile  = w >> 7;
    int r     = w & 127;
    int chunk = lane >> 4;                       // cols 0..63 -> 0, 64..127 -> 1
    uint32_t off = tile_off64((uint32_t)r, (uint32_t)((lane & 15) * 4));
    size_t base = ((size_t)tile * 2 + chunk) * 16384;
    *(uint2*)(g_aggH + base + off) = uh;
    *(uint2*)(g_aggL + base + off) = ul;
}

// ============ layer: tcgen05 dual-GEMM + bias + LN + ReLU ============
__global__ void __launch_bounds__(GEMM_THREADS, 1)
k_layer_mma(const float* __restrict__ hin, float* __restrict__ hout,
            const float* __restrict__ Wl, const float* __restrict__ bl,
            const float* __restrict__ Wr, const float* __restrict__ gamma,
            const float* __restrict__ beta) {
    extern __shared__ char smem[];
    uint32_t sb = smem_u32(smem);
    int tid = threadIdx.x, wid = tid >> 5, lane = tid & 31;

#if USE_TCGEN05
    if (wid == 0) tmem_alloc(sb + SM_TMEM, 128);
    if (tid == 0) { mbar_init(sb + SM_MBAR, 1); mbar_init(sb + SM_MBAR + 8, 1); }
    __syncthreads();
    uint32_t tmem;
    asm volatile("ld.shared.b32 %0, [%1];" : "=r"(tmem) : "r"(sb + SM_TMEM));

    if (tid < H) {
        ((float*)(smem + SM_BIAS))[tid] = bl[tid];
        ((float*)(smem + SM_GAM ))[tid] = gamma[tid];
        ((float*)(smem + SM_BET ))[tid] = beta[tid];
    }
    for (int idx = tid; idx < 8192; idx += GEMM_THREADS) {
        int m   = idx >> 12;
        int rem = idx & 4095;
        int c   = rem >> 5;
        int f   = rem & 31;
        float4 v = ((const float4*)(m ? Wr : Wl))[c*32 + f];
        uint32_t kcol = (uint32_t)(m*128 + f*4);
        uint2 uh, ul; cvt_split(v, uh, ul);
        uint32_t off = tile_off((uint32_t)c, kcol);
        *(uint2*)(smem + SM_BH + off) = uh;
        *(uint2*)(smem + SM_BL + off) = ul;
    }

    uint64_t dBh = make_desc(sb + SM_BH), dBl = make_desc(sb + SM_BL);
    const float* bls = (const float*)(smem + SM_BIAS);
    const float* gms = (const float*)(smem + SM_GAM);
    const float* bts = (const float*)(smem + SM_BET);
    float* eps = (float*)(smem + SM_EPI);

    int cnt[2] = {0,0}, ws[2] = {0,0};
    int r_row = tid >> 2, q = tid & 3;
    const float4 zf4 = make_float4(0.f,0.f,0.f,0.f);
    // prefetch registers: agg chunks (uint4 copies) / h chunks (float4 convert)
    uint4 ph0, ph1, pl0, pl1;
    float4 v0, v1, v2, v3;

    // agg chunk prefetch: verbatim 32B/thread from pre-swizzled region
#define LD_AGG(TILE, C) do {                                                  \
        const uint4* _sH = (const uint4*)(g_aggH + ((size_t)(TILE)*2 + (C))*16384); \
        const uint4* _sL = (const uint4*)(g_aggL + ((size_t)(TILE)*2 + (C))*16384); \
        ph0 = _sH[tid*2]; ph1 = _sH[tid*2+1];                                 \
        pl0 = _sL[tid*2]; pl1 = _sL[tid*2+1];                                 \
    } while (0)
#define LD_H(TB, C) do {                                                      \
        const float4* _s4 = (const float4*)hin;                               \
        int _nd = (TB) + r_row;                                               \
        bool _val = _nd < NN;                                                 \
        int _fb = ((C) & 1) * 16 + q * 4;                                     \
        v0 = _val ? _s4[_nd*32 + _fb + 0] : zf4;                              \
        v1 = _val ? _s4[_nd*32 + _fb + 1] : zf4;                              \
        v2 = _val ? _s4[_nd*32 + _fb + 2] : zf4;                              \
        v3 = _val ? _s4[_nd*32 + _fb + 3] : zf4;                              \
    } while (0)

    int tile0 = blockIdx.x;
    if (tile0 < NT) LD_AGG(tile0, 0);

    for (int tile = tile0; tile < NT; tile += gridDim.x) {
        int tb = tile * TILE_M;

#pragma unroll
        for (int c = 0; c < 4; c++) {
            int p = c & 1;
            uint32_t mb = sb + SM_MBAR + p*8;
            if (ws[p] < cnt[p]) { mbar_wait(mb, (cnt[p]-1) & 1); ws[p] = cnt[p]; }
            if (c < 2) {
                // straight copy from pre-swizzled gmem
                uint4* dH = (uint4*)(smem + SM_A + p*32768);
                uint4* dL = dH + 1024;    // +16KB
                dH[tid*2] = ph0; dH[tid*2+1] = ph1;
                dL[tid*2] = pl0; dL[tid*2+1] = pl1;
            } else {
                char* aH = smem + SM_A + p*32768;
                char* aL = aH + 16384;
                uint2 uh, ul; uint32_t off;
                off = tile_off64((uint32_t)r_row, (uint32_t)(q*16 + 0));
                cvt_split(v0, uh, ul); *(uint2*)(aH+off)=uh; *(uint2*)(aL+off)=ul;
                off = tile_off64((uint32_t)r_row, (uint32_t)(q*16 + 4));
                cvt_split(v1, uh, ul); *(uint2*)(aH+off)=uh; *(uint2*)(aL+off)=ul;
                off = tile_off64((uint32_t)r_row, (uint32_t)(q*16 + 8));
                cvt_split(v2, uh, ul); *(uint2*)(aH+off)=uh; *(uint2*)(aL+off)=ul;
                off = tile_off64((uint32_t)r_row, (uint32_t)(q*16 + 12));
                cvt_split(v3, uh, ul); *(uint2*)(aH+off)=uh; *(uint2*)(aL+off)=ul;
            }
            // prefetch next chunk / next tile's chunk 0
            if (c == 0)      LD_AGG(tile, 1);
            else if (c == 1) LD_H(tb, 2);
            else if (c == 2) LD_H(tb, 3);
            else {
                int nt2 = tile + gridDim.x;
                if (nt2 < NT) LD_AGG(nt2, 0);
            }
            fence_async_smem();
            __syncthreads();
            if (wid == 0 && elect_one()) {
                uint64_t dAh = make_desc(sb + SM_A + p*32768);
                uint64_t dAl = make_desc(sb + SM_A + p*32768 + 16384);
#pragma unroll
                for (int k = 0; k < 4; k++) {
                    uint64_t ao = (uint64_t)(k*2);
                    int ks = c*4 + k;
                    uint64_t bo = (uint64_t)((ks >> 2)*1024 + (ks & 3)*2);
                    mma_bf16_ss(tmem, dAh + ao, dBh + bo, MMA_IDESC, (c==0 && k==0) ? 0u : 1u);
                    mma_bf16_ss(tmem, dAh + ao, dBl + bo, MMA_IDESC, 1u);
                    mma_bf16_ss(tmem, dAl + ao, dBh + bo, MMA_IDESC, 1u);
                }
                tc_commit(mb);
            }
            cnt[p]++;
        }

        if (ws[1] < cnt[1]) { mbar_wait(sb + SM_MBAR + 8, (cnt[1]-1) & 1); ws[1] = cnt[1]; }
        tc_fence_after();

        if (wid < 4) {
            int row = wid * 32 + lane;
            float s1 = 0.f, s2 = 0.f;
            uint32_t d[32];
#pragma unroll
            for (int g = 0; g < 4; g++) {
                ldtm_x32(d, tmem + g * 32);
                tc_wait_ld();
#pragma unroll
                for (int c = 0; c < 32; c++) {
                    float v = __uint_as_float(d[c]) + bls[g*32 + c];
                    s1 += v; s2 += v * v;
                }
            }
            float mu  = s1 * (1.0f / H);
            float var = s2 * (1.0f / H) - mu * mu;
            float rs  = rsqrtf(var + LN_EPS);
#pragma unroll
            for (int g = 0; g < 4; g++) {
                ldtm_x32(d, tmem + g * 32);
                tc_wait_ld();
#pragma unroll
                for (int c = 0; c < 32; c++) {
                    float v = __uint_as_float(d[c]) + bls[g*32 + c];
                    eps[row*129 + g*32 + c] =
                        fmaxf((v - mu) * rs * gms[g*32 + c] + bts[g*32 + c], 0.f);
                }
            }
            tc_fence_before();
        }
        __syncthreads();
        {
            int r0 = wid * 8;
#pragma unroll
            for (int rr = 0; rr < 8; rr++) {
                int r = r0 + rr;
                int node = tb + r;
                if (node < NN) {
#pragma unroll
                    for (int u = 0; u < 4; u++)
                        hout[(size_t)node*H + u*32 + lane] = eps[r*129 + u*32 + lane];
                }
            }
        }
        __syncthreads();
    }
#undef LD_AGG
#undef LD_H
    if (ws[0] < cnt[0]) { mbar_wait(sb + SM_MBAR,     (cnt[0]-1) & 1); ws[0] = cnt[0]; }
    if (ws[1] < cnt[1]) { mbar_wait(sb + SM_MBAR + 8, (cnt[1]-1) & 1); ws[1] = cnt[1]; }
    __syncthreads();
    if (wid == 0) tmem_dealloc(tmem, 128);

#else  // ===== FFMA fallback (compute_103 PTX pass; never selected on GB300) =====
    float* sW = (float*)(smem + 2048);
    float* sA = sW + 256*H;
    for (int idx = tid; idx < H*H; idx += GEMM_THREADS) {
        int c = idx >> 7, k = idx & 127;
        sW[k*H + c]     = Wl[idx];
        sW[(k+H)*H + c] = Wr[idx];
    }
    __syncthreads();
    float4 blv = ((const float4*)bl)[lane];
    float4 gv  = ((const float4*)gamma)[lane];
    float4 bv  = ((const float4*)beta)[lane];
    const float4* h4 = (const float4*)hin;
    float* sAw = sA + wid*256;
    for (int node = blockIdx.x*GEMM_WARPS + wid; node < NN; node += GEMM_BLOCKS*GEMM_WARPS) {
        // reconstruct agg from pre-swizzled bf16 hi/lo
        {
            int tile  = node >> 7, r = node & 127;
            int chunk = lane >> 4;
            uint32_t off = tile_off64((uint32_t)r, (uint32_t)((lane & 15) * 4));
            size_t base = ((size_t)tile * 2 + chunk) * 16384;
            uint2 uh = *(uint2*)(g_aggH + base + off);
            uint2 ul = *(uint2*)(g_aggL + base + off);
            __nv_bfloat162 h01 = *(__nv_bfloat162*)&uh.x;
            __nv_bfloat162 h23 = *(__nv_bfloat162*)&uh.y;
            __nv_bfloat162 l01 = *(__nv_bfloat162*)&ul.x;
            __nv_bfloat162 l23 = *(__nv_bfloat162*)&ul.y;
            float4 a;
            a.x = __bfloat162float(h01.x) + __bfloat162float(l01.x);
            a.y = __bfloat162float(h01.y) + __bfloat162float(l01.y);
            a.z = __bfloat162float(h23.x) + __bfloat162float(l23.x);
            a.w = __bfloat162float(h23.y) + __bfloat162float(l23.y);
            *(float4*)(sAw + lane*4) = a;
        }
        *(float4*)(sAw + 128 + lane*4) = h4[node*32 + lane];
        __syncwarp();
        float4 acc = make_float4(0.f,0.f,0.f,0.f);
        for (int k = 0; k < 256; k++) {
            float aa = sAw[k];
            float4 wv = *(const float4*)(sW + k*H + lane*4);
            acc.x += aa*wv.x; acc.y += aa*wv.y; acc.z += aa*wv.z; acc.w += aa*wv.w;
        }
        acc.x += blv.x; acc.y += blv.y; acc.z += blv.z; acc.w += blv.w;
        float s1 = acc.x + acc.y + acc.z + acc.w;
        float s2 = acc.x*acc.x + acc.y*acc.y + acc.z*acc.z + acc.w*acc.w;
        for (int o = 16; o > 0; o >>= 1) {
            s1 += __shfl_xor_sync(0xffffffffu, s1, o);
            s2 += __shfl_xor_sync(0xffffffffu, s2, o);
        }
        float mu  = s1 * (1.0f/H);
        float var = s2 * (1.0f/H) - mu*mu;
        float r   = rsqrtf(var + LN_EPS);
        float4 o4;
        o4.x = fmaxf((acc.x - mu)*r*gv.x + bv.x, 0.0f);
        o4.y = fmaxf((acc.y - mu)*r*gv.y + bv.y, 0.0f);
        o4.z = fmaxf((acc.z - mu)*r*gv.z + bv.z, 0.0f);
        o4.w = fmaxf((acc.w - mu)*r*gv.w + bv.w, 0.0f);
        ((float4*)hout)[(size_t)node*32 + lane] = o4;
        __syncwarp();
    }
#endif
}

// ============ final: tcgen05 projection (N=64) + log_softmax (prefetch-pipelined) ============
__global__ void __launch_bounds__(GEMM_THREADS, 1)
k_final_mma(const float* __restrict__ hin, const float* __restrict__ Wf,
            const float* __restrict__ bf, float* __restrict__ out) {
    extern __shared__ char smem[];
    uint32_t sb = smem_u32(smem);
    int tid = threadIdx.x, wid = tid >> 5, lane = tid & 31;

#if USE_TCGEN05
    if (wid == 0) tmem_alloc(sb + SMF_TMEM, 128);
    if (tid == 0) { mbar_init(sb + SMF_MBAR, 1); mbar_init(sb + SMF_MBAR + 8, 1); }
    __syncthreads();
    uint32_t tmem;
    asm volatile("ld.shared.b32 %0, [%1];" : "=r"(tmem) : "r"(sb + SMF_TMEM));

    if (tid < NC) ((float*)(smem + SMF_BF))[tid] = bf[tid];
    for (int idx = tid; idx < 2048; idx += GEMM_THREADS) {
        int c = idx >> 5, f = idx & 31;
        float4 v = ((const float4*)Wf)[c*32 + f];
        uint2 uh, ul; cvt_split(v, uh, ul);
        uint32_t off = tile_off8((uint32_t)c, (uint32_t)(f*4));
        *(uint2*)(smem + SMF_BH + off) = uh;
        *(uint2*)(smem + SMF_BL + off) = ul;
    }

    uint64_t dBh = make_desc(sb + SMF_BH), dBl = make_desc(sb + SMF_BL);
    const float* bfs = (const float*)(smem + SMF_BF);

    int cnt[2] = {0,0}, ws[2] = {0,0};
    int r_row = tid >> 2, q = tid & 3;
    const float4 zf4 = make_float4(0.f,0.f,0.f,0.f);
    float4 v0, v1, v2, v3;

#define LD_CHUNKF(TB, C) do {                                           \
        const float4* _s4 = (const float4*)hin;                         \
        int _nd = (TB) + r_row;                                         \
        bool _val = _nd < NN;                                           \
        int _fb = (C) * 16 + q * 4;                                     \
        v0 = _val ? _s4[_nd*32 + _fb + 0] : zf4;                        \
        v1 = _val ? _s4[_nd*32 + _fb + 1] : zf4;                        \
        v2 = _val ? _s4[_nd*32 + _fb + 2] : zf4;                        \
        v3 = _val ? _s4[_nd*32 + _fb + 3] : zf4;                        \
    } while (0)

    int tile0 = blockIdx.x;
    if (tile0 < NT) LD_CHUNKF(tile0 * TILE_M, 0);

    for (int tile = tile0; tile < NT; tile += gridDim.x) {
        int tb = tile * TILE_M;
#pragma unroll
        for (int c = 0; c < 2; c++) {
            int p = c;
            uint32_t mb = sb + SMF_MBAR + p*8;
            if (ws[p] < cnt[p]) { mbar_wait(mb, (cnt[p]-1) & 1); ws[p] = cnt[p]; }
            {
                char* aH = smem + SMF_A + p*32768;
                char* aL = aH + 16384;
                uint2 uh, ul; uint32_t off;
                off = tile_off64((uint32_t)r_row, (uint32_t)(q*16 + 0));
                cvt_split(v0, uh, ul); *(uint2*)(aH+off)=uh; *(uint2*)(aL+off)=ul;
                off = tile_off64((uint32_t)r_row, (uint32_t)(q*16 + 4));
                cvt_split(v1, uh, ul); *(uint2*)(aH+off)=uh; *(uint2*)(aL+off)=ul;
                off = tile_off64((uint32_t)r_row, (uint32_t)(q*16 + 8));
                cvt_split(v2, uh, ul); *(uint2*)(aH+off)=uh; *(uint2*)(aL+off)=ul;
                off = tile_off64((uint32_t)r_row, (uint32_t)(q*16 + 12));
                cvt_split(v3, uh, ul); *(uint2*)(aH+off)=uh; *(uint2*)(aL+off)=ul;
            }
            if (c == 0) {
                LD_CHUNKF(tb, 1);
            } else {
                int nt2 = tile + gridDim.x;
                if (nt2 < NT) LD_CHUNKF(nt2 * TILE_M, 0);
            }
            fence_async_smem();
            __syncthreads();
            if (wid == 0 && elect_one()) {
                uint64_t dAh = make_desc(sb + SMF_A + p*32768);
                uint64_t dAl = make_desc(sb + SMF_A + p*32768 + 16384);
#pragma unroll
                for (int k = 0; k < 4; k++) {
                    uint64_t ao = (uint64_t)(k*2);
                    int ks = c*4 + k;
                    uint64_t bo = (uint64_t)((ks >> 2)*512 + (ks & 3)*2);
                    mma_bf16_ss(tmem, dAh + ao, dBh + bo, MMA_IDESC64, (c==0 && k==0) ? 0u : 1u);
                    mma_bf16_ss(tmem, dAh + ao, dBl + bo, MMA_IDESC64, 1u);
                    mma_bf16_ss(tmem, dAl + ao, dBh + bo, MMA_IDESC64, 1u);
                }
                tc_commit(mb);
            }
            cnt[p]++;
        }

        if (ws[1] < cnt[1]) { mbar_wait(sb + SMF_MBAR + 8, (cnt[1]-1) & 1); ws[1] = cnt[1]; }
        tc_fence_after();

        if (wid < 4) {
            int row = wid * 32 + lane;
            int node = tb + row;
            uint32_t d0[32], d1[32];
            ldtm_x32(d0, tmem);
            ldtm_x32(d1, tmem + 32);
            tc_wait_ld();
            float l0[32], l1[32];
            float m = -1e30f;
#pragma unroll
            for (int j = 0; j < 32; j++) {
                l0[j] = __uint_as_float(d0[j]) + bfs[j];
                l1[j] = __uint_as_float(d1[j]) + bfs[32 + j];
                m = fmaxf(m, fmaxf(l0[j], l1[j]));
            }
            float se = 0.f;
#pragma unroll
            for (int j = 0; j < 32; j++) se += expf(l0[j] - m) + expf(l1[j] - m);
            float lse = logf(se) + m;
            if (node < NN) {
#pragma unroll
                for (int j = 0; j < 32; j++) {
                    out[(size_t)node*NC + j]      = l0[j] - lse;
                    out[(size_t)node*NC + 32 + j] = l1[j] - lse;
                }
            }
            tc_fence_before();
        }
        __syncthreads();
    }
#undef LD_CHUNKF
    if (ws[0] < cnt[0]) { mbar_wait(sb + SMF_MBAR,     (cnt[0]-1) & 1); ws[0] = cnt[0]; }
    if (ws[1] < cnt[1]) { mbar_wait(sb + SMF_MBAR + 8, (cnt[1]-1) & 1); ws[1] = cnt[1]; }
    __syncthreads();
    if (wid == 0) tmem_dealloc(tmem, 128);

#else  // ===== FFMA fallback =====
    __shared__ float sW[H*NC];
    for (int idx = tid; idx < NC*H; idx += GEMM_THREADS) {
        int c = idx >> 7, k = idx & 127;
        sW[k*NC + c] = Wf[idx];
    }
    __syncthreads();
    float bf0 = bf[lane], bf1 = bf[32 + lane];
    for (int node = blockIdx.x*GEMM_WARPS + wid; node < NN; node += GEMM_BLOCKS*GEMM_WARPS) {
        float al[4];
#pragma unroll
        for (int q2=0;q2<4;q2++) al[q2] = hin[(size_t)node*H + q2*32 + lane];
        float acc0 = 0.f, acc1 = 0.f;
#pragma unroll
        for (int q2=0;q2<4;q2++) {
            float aq = al[q2];
#pragma unroll
            for (int kk=0;kk<32;kk++) {
                float a = __shfl_sync(0xffffffffu, aq, kk);
                acc0 += a * sW[(q2*32+kk)*NC + lane];
                acc1 += a * sW[(q2*32+kk)*NC + 32 + lane];
            }
        }
        acc0 += bf0; acc1 += bf1;
        float m = fmaxf(acc0, acc1);
#pragma unroll
        for (int o=16;o>0;o>>=1) m = fmaxf(m, __shfl_xor_sync(0xffffffffu, m, o));
        float se = expf(acc0 - m) + expf(acc1 - m);
#pragma unroll
        for (int o=16;o>0;o>>=1) se += __shfl_xor_sync(0xffffffffu, se, o);
        float lse = logf(se);
        out[(size_t)node*NC + lane]      = acc0 - m - lse;
        out[(size_t)node*NC + 32 + lane] = acc1 - m - lse;
    }
#endif
}

extern "C" void kernel_launch(void* const* d_in, const int* in_sizes, int n_in,
                              void* d_out, int out_size) {
    const float* x     = (const float*)d_in[0];
    const int*   ei    = (const int*)  d_in[1];
    const float* Wl    = (const float*)d_in[2];
    const float* bl    = (const float*)d_in[3];
    const float* Wr    = (const float*)d_in[4];
    const float* gamma = (const float*)d_in[5];
    const float* beta  = (const float*)d_in[6];
    const float* Wf    = (const float*)d_in[7];
    const float* bf    = (const float*)d_in[8];
    float* out = (float*)d_out;

    cudaFuncSetAttribute(k_layer_mma, cudaFuncAttributeMaxDynamicSharedMemorySize, SM_TOTAL);
    cudaFuncSetAttribute(k_final_mma, cudaFuncAttributeMaxDynamicSharedMemorySize, SMF_TOTAL);

    float *hA, *hB;
    cudaGetSymbolAddress((void**)&hA, g_hA);
    cudaGetSymbolAddress((void**)&hB, g_hB);

    // g_deg is zero here (BSS init on first call; k_zero_deg at end of every call)
    k_count  <<<(NE+255)/256, 256>>>(ei);          // launch 0
    k_scan   <<<1, 1024>>>();                       // launch 1
    k_scatter<<<(NE+255)/256, 256>>>(ei);          // launch 2

    const float* hin = x;
    float* houts[3] = {hA, hB, hA};
    for (int i=0;i<3;i++) {
        k_agg<<<(NN+7)/8, 256>>>(hin);             // launch 3 (i=0) -> ncu target
        k_layer_mma<<<GEMM_BLOCKS, GEMM_THREADS, SM_TOTAL>>>(hin, houts[i],
            Wl + i*H*H, bl + i*H, Wr + i*H*H, gamma + i*H, beta + i*H);
        hin = houts[i];
    }
    k_final_mma<<<GEMM_BLOCKS, GEMM_THREADS, SMF_TOTAL>>>(hin, Wf, bf, out);
    k_zero_deg<<<(NN+255)/256, 256>>>();           // reset for next call
}